// round 17
// baseline (speedup 1.0000x reference)
#include <cuda_runtime.h>
#include <cuda_fp16.h>
#include <math.h>
#include <stdint.h>

#define HID 1024
#define NHEADS 16
#define HEADDIM 64
#define BATCH 2
#define SEQ 2048
#define MROWS (BATCH * SEQ)   // 4096

#define QSCALE (0.125f * 1.4426950408889634f)   // 1/sqrt(64) * log2(e), folded into q

typedef __half fp16;

// ---------------- scratch ----------------
__device__ fp16 g_qin [(size_t)MROWS * HID];
__device__ fp16 g_kvin[(size_t)MROWS * HID];
__device__ fp16 g_q   [(size_t)MROWS * HID];
__device__ fp16 g_kv  [(size_t)MROWS * 2 * HID];
__device__ fp16 g_y   [(size_t)MROWS * HID];
__device__ fp16 g_wqT [(size_t)HID * HID];
__device__ fp16 g_wkvT[(size_t)2 * HID * HID];
__device__ fp16 g_wcT [(size_t)HID * HID];

// ---------------- PTX helpers ----------------
__device__ __forceinline__ uint32_t smem_u32(const void* p) {
    uint32_t a;
    asm("{ .reg .u64 t; cvta.to.shared.u64 t, %1; cvt.u32.u64 %0, t; }" : "=r"(a) : "l"(p));
    return a;
}
__device__ __forceinline__ void cp16(uint32_t s, const void* g) {
    asm volatile("cp.async.cg.shared.global [%0], [%1], 16;" :: "r"(s), "l"(g));
}
#define CP_COMMIT() asm volatile("cp.async.commit_group;" ::: "memory")
#define CP_WAIT1()  asm volatile("cp.async.wait_group 1;" ::: "memory")
#define CP_WAIT2()  asm volatile("cp.async.wait_group 2;" ::: "memory")

__device__ __forceinline__ void ldsm4(uint32_t* r, uint32_t a) {
    asm volatile("ldmatrix.sync.aligned.m8n8.x4.shared.b16 {%0,%1,%2,%3}, [%4];"
                 : "=r"(r[0]), "=r"(r[1]), "=r"(r[2]), "=r"(r[3]) : "r"(a));
}
__device__ __forceinline__ void ldsm4t(uint32_t* r, uint32_t a) {
    asm volatile("ldmatrix.sync.aligned.m8n8.x4.trans.shared.b16 {%0,%1,%2,%3}, [%4];"
                 : "=r"(r[0]), "=r"(r[1]), "=r"(r[2]), "=r"(r[3]) : "r"(a));
}
__device__ __forceinline__ void mma16816(float* d, const uint32_t* a, const uint32_t* b) {
    asm volatile(
        "mma.sync.aligned.m16n8k16.row.col.f32.f16.f16.f32 "
        "{%0,%1,%2,%3}, {%4,%5,%6,%7}, {%8,%9}, {%0,%1,%2,%3};"
        : "+f"(d[0]), "+f"(d[1]), "+f"(d[2]), "+f"(d[3])
        : "r"(a[0]), "r"(a[1]), "r"(a[2]), "r"(a[3]), "r"(b[0]), "r"(b[1]));
}

__device__ __forceinline__ uint32_t pack2(float a, float b) {
    __half2 t = __floats2half2_rn(a, b);
    return *(uint32_t*)&t;
}

// ================= fp16 mma.sync GEMM core (BK=64, 3-stage) =================
// C[M,N] = A[M,K] . B^T, B stored [N,K] row-major (pre-transposed).
// CTA tile 128x128, 8 warps (4m x 2n), warp tile 32x64. 2 CTAs/SM.
#define GP    144     // smem pitch bytes per 64-fp16 row (conflict-free LDSM)
#define GMAT  (128 * GP)      // 18432
#define GSTG  (2 * GMAT)      // A + B per stage = 36864
#define GSMEM (3 * GSTG)      // 110592

template<int MODE>   // 0: fp32 out, 1: fp16 out (scaled)
__device__ __forceinline__ void gemm_core(
    uint32_t sb,
    const fp16* __restrict__ A, const fp16* __restrict__ B,
    float* __restrict__ Cf, fp16* __restrict__ Ch,
    int N, int K, int m0, int n0, float scale) {
    const int tid = threadIdx.x, lane = tid & 31, wid = tid >> 5;
    const int wm = (wid >> 1) << 5, wn = (wid & 1) << 6;

    const int arow  = (lane & 7) + ((lane >> 3) & 1) * 8;
    const int akoff = ((lane >> 4) << 3);
    const int brow  = (lane & 7) + ((lane >> 4) << 3);
    const int bkoff = ((lane >> 3) & 1) * 8;

    float acc[2][8][4];
    #pragma unroll
    for (int i = 0; i < 2; i++)
        #pragma unroll
        for (int j = 0; j < 8; j++)
            #pragma unroll
            for (int r = 0; r < 4; r++) acc[i][j][r] = 0.f;

    const int NCH = K >> 6;    // BK = 64

    // per-thread load coordinates (1024 cp16 per matrix, 4/thread)
    const int lrow = tid >> 3, lc = (tid & 7);

    // prologue: load chunks 0 and 1 into stages 0, 1
    #pragma unroll
    for (int st = 0; st < 2; st++) {
        uint32_t d = sb + st * GSTG;
        int k0 = st << 6;
        #pragma unroll
        for (int i = 0; i < 4; i++) {
            int row = lrow + i * 32;
            uint32_t off = row * GP + lc * 16;
            cp16(d + off,        A + (size_t)(m0 + row) * K + k0 + lc * 8);
            cp16(d + GMAT + off, B + (size_t)(n0 + row) * K + k0 + lc * 8);
        }
        CP_COMMIT();
    }

    int sc = 0, sl = 2;    // compute stage, load stage
    for (int ch = 0; ch < NCH; ch++) {
        if (ch + 2 < NCH) {
            uint32_t d = sb + sl * GSTG;
            int k0 = (ch + 2) << 6;
            #pragma unroll
            for (int i = 0; i < 4; i++) {
                int row = lrow + i * 32;
                uint32_t off = row * GP + lc * 16;
                cp16(d + off,        A + (size_t)(m0 + row) * K + k0 + lc * 8);
                cp16(d + GMAT + off, B + (size_t)(n0 + row) * K + k0 + lc * 8);
            }
        }
        CP_COMMIT();
        CP_WAIT2();          // chunk ch resident
        __syncthreads();

        const uint32_t base = sb + sc * GSTG;
        #pragma unroll
        for (int kk = 0; kk < 4; kk++) {
            uint32_t af[2][4];
            #pragma unroll
            for (int sm = 0; sm < 2; sm++) {
                uint32_t aoff = (wm + sm * 16 + arow) * GP + (kk * 16 + akoff) * 2;
                ldsm4(af[sm], base + aoff);
            }
            uint32_t bf4[4][4];
            #pragma unroll
            for (int q = 0; q < 4; q++) {
                uint32_t boff = (wn + q * 16 + brow) * GP + (kk * 16 + bkoff) * 2;
                ldsm4(bf4[q], base + GMAT + boff);
            }
            #pragma unroll
            for (int sm = 0; sm < 2; sm++)
                #pragma unroll
                for (int nt = 0; nt < 8; nt++)
                    mma16816(acc[sm][nt], af[sm], &bf4[nt >> 1][(nt & 1) << 1]);
        }
        __syncthreads();     // stage sc free for reuse

        sc = (sc == 2) ? 0 : sc + 1;
        sl = (sl == 2) ? 0 : sl + 1;
    }

    const int r0 = wm + (lane >> 2);
    const int c0 = wn + ((lane & 3) << 1);
    #pragma unroll
    for (int sm = 0; sm < 2; sm++)
        #pragma unroll
        for (int nt = 0; nt < 8; nt++) {
            int row = m0 + r0 + sm * 16;
            int col = n0 + c0 + nt * 8;
            if (MODE == 0) {
                *(float2*)(Cf + (size_t)row * N + col) =
                    make_float2(acc[sm][nt][0], acc[sm][nt][1]);
                *(float2*)(Cf + (size_t)(row + 8) * N + col) =
                    make_float2(acc[sm][nt][2], acc[sm][nt][3]);
            } else {
                *(uint32_t*)(Ch + (size_t)row * N + col) =
                    pack2(acc[sm][nt][0] * scale, acc[sm][nt][1] * scale);
                *(uint32_t*)(Ch + (size_t)(row + 8) * N + col) =
                    pack2(acc[sm][nt][2] * scale, acc[sm][nt][3] * scale);
            }
        }
}

// merged q-proj + kv-proj (one launch, no wave tails)
__global__ __launch_bounds__(256, 2)
void proj_gemm(const fp16* __restrict__ qin, const fp16* __restrict__ kvin,
               const fp16* __restrict__ wq, const fp16* __restrict__ wkv,
               fp16* __restrict__ q, fp16* __restrict__ kv) {
    extern __shared__ __align__(128) char smem[];
    const uint32_t sb = smem_u32(smem);
    const int bx = blockIdx.x, m0 = blockIdx.y << 7;
    if (bx < HID / 128) {
        gemm_core<1>(sb, qin, wq, nullptr, q, HID, HID, m0, bx << 7, QSCALE);
    } else {
        gemm_core<1>(sb, kvin, wkv, nullptr, kv, 2 * HID, HID, m0, (bx - HID / 128) << 7, 1.0f);
    }
}

__global__ __launch_bounds__(256, 2)
void out_gemm(const fp16* __restrict__ y, const fp16* __restrict__ wc,
              float* __restrict__ out) {
    extern __shared__ __align__(128) char smem[];
    const uint32_t sb = smem_u32(smem);
    gemm_core<0>(sb, y, wc, out, nullptr, HID, HID, blockIdx.y << 7, blockIdx.x << 7, 0.f);
}

// ================= flash attention on fp16 mma.sync =================
// CTA: 64 queries x one (b,h), 128 threads / 4 warps. 64-row KV chunks,
// 2 stages. 3 CTAs/SM (smem 46080x3 = 138KB).
#define AP     144                 // pitch bytes per 64-fp16 row
#define AQMAT  (64 * AP)           // 9216  (Q tile: 64 rows)
#define AKM    (64 * AP)           // one K or V matrix (64 rows) = 9216
#define ASTG   (2 * AKM)           // K+V per stage = 18432
#define ASMEM  (AQMAT + 2 * ASTG)  // 46080

__global__ __launch_bounds__(128, 3)
void attn_mma(const fp16* __restrict__ q, const fp16* __restrict__ kv,
              fp16* __restrict__ y) {
    extern __shared__ __align__(128) char smem[];
    const uint32_t sb = smem_u32(smem);
    const int tid = threadIdx.x, lane = tid & 31, wid = tid >> 5;
    const int bh = blockIdx.y;
    const int b = bh >> 4, h = bh & 15;
    const int q0 = blockIdx.x << 6;      // 64-query tiles

    const int arow  = (lane & 7) + ((lane >> 3) & 1) * 8;
    const int akoff = ((lane >> 4) << 3);
    const int brow  = (lane & 7) + ((lane >> 4) << 3);
    const int bkoff = ((lane >> 3) & 1) * 8;

    const uint32_t sQ  = sb;
    const uint32_t sKV = sb + AQMAT;

    // --- load Q tile (64 x 64): 512 cp16, 4/thread ---
    #pragma unroll
    for (int i = 0; i < 4; i++) {
        int idx = tid + (i << 7);
        int row = idx >> 3, c = idx & 7;
        cp16(sQ + row * AP + c * 16,
             q + (size_t)(b * SEQ + q0 + row) * HID + h * HEADDIM + c * 8);
    }
    CP_COMMIT();

    // --- preload KV chunk 0 (64 rows of K and V): 4 (K,V) pairs / thread ---
    const size_t kvrow0 = (size_t)(b * SEQ);
    #pragma unroll
    for (int i = 0; i < 4; i++) {
        int idx = tid + (i << 7);
        int row = idx >> 3, c = idx & 7;
        uint32_t off = row * AP + c * 16;
        size_t gk = (kvrow0 + row) * (2 * HID) + h * HEADDIM + c * 8;
        cp16(sKV + off,       kv + gk);
        cp16(sKV + AKM + off, kv + gk + HID);
    }
    CP_COMMIT();
    CP_WAIT1();        // Q resident
    __syncthreads();

    uint32_t qf[4][4];
    #pragma unroll
    for (int kk = 0; kk < 4; kk++)
        ldsm4(qf[kk], sQ + (wid * 16 + arow) * AP + (kk * 16 + akoff) * 2);

    float o[8][4];
    #pragma unroll
    for (int i = 0; i < 8; i++)
        #pragma unroll
        for (int r = 0; r < 4; r++) o[i][r] = 0.f;
    float m0_ = -INFINITY, m1_ = -INFINITY, l0_ = 0.f, l1_ = 0.f;

    const int NIT = SEQ / 64;
    for (int ch = 0; ch < NIT; ch++) {
        if (ch + 1 < NIT) {
            uint32_t d = sKV + ((ch + 1) & 1) * ASTG;
            int t0 = (ch + 1) << 6;
            #pragma unroll
            for (int i = 0; i < 4; i++) {
                int idx = tid + (i << 7);
                int row = idx >> 3, c = idx & 7;
                uint32_t off = row * AP + c * 16;
                size_t gk = (kvrow0 + t0 + row) * (2 * HID) + h * HEADDIM + c * 8;
                cp16(d + off,       kv + gk);
                cp16(d + AKM + off, kv + gk + HID);
            }
        }
        CP_COMMIT();
        CP_WAIT1();
        __syncthreads();

        const uint32_t sK = sKV + (ch & 1) * ASTG;
        const uint32_t sV = sK + AKM;

        // ---- S over 64 keys ----
        float s[8][4];
        #pragma unroll
        for (int i = 0; i < 8; i++)
            #pragma unroll
            for (int r = 0; r < 4; r++) s[i][r] = 0.f;

        #pragma unroll
        for (int kk = 0; kk < 4; kk++) {
            uint32_t kb[4][4];
            #pragma unroll
            for (int g = 0; g < 4; g++)
                ldsm4(kb[g], sK + (g * 16 + brow) * AP + (kk * 16 + bkoff) * 2);
            #pragma unroll
            for (int nt = 0; nt < 8; nt++)
                mma16816(s[nt], qf[kk], &kb[nt >> 1][(nt & 1) << 1]);
        }

        // ---- online softmax (exp2 domain) ----
        float mx0 = -INFINITY, mx1 = -INFINITY;
        #pragma unroll
        for (int nt = 0; nt < 8; nt++) {
            mx0 = fmaxf(mx0, fmaxf(s[nt][0], s[nt][1]));
            mx1 = fmaxf(mx1, fmaxf(s[nt][2], s[nt][3]));
        }
        mx0 = fmaxf(mx0, __shfl_xor_sync(0xffffffffu, mx0, 1));
        mx0 = fmaxf(mx0, __shfl_xor_sync(0xffffffffu, mx0, 2));
        mx1 = fmaxf(mx1, __shfl_xor_sync(0xffffffffu, mx1, 1));
        mx1 = fmaxf(mx1, __shfl_xor_sync(0xffffffffu, mx1, 2));
        float mn0 = fmaxf(m0_, mx0), mn1 = fmaxf(m1_, mx1);
        float corr0 = exp2f(m0_ - mn0), corr1 = exp2f(m1_ - mn1);
        m0_ = mn0; m1_ = mn1;

        float rs0 = 0.f, rs1 = 0.f;
        #pragma unroll
        for (int nt = 0; nt < 8; nt++) {
            s[nt][0] = exp2f(s[nt][0] - mn0); rs0 += s[nt][0];
            s[nt][1] = exp2f(s[nt][1] - mn0); rs0 += s[nt][1];
            s[nt][2] = exp2f(s[nt][2] - mn1); rs1 += s[nt][2];
            s[nt][3] = exp2f(s[nt][3] - mn1); rs1 += s[nt][3];
        }
        uint32_t ph[4][4];
        #pragma unroll
        for (int j = 0; j < 4; j++) {
            ph[j][0] = pack2(s[2*j][0], s[2*j][1]);
            ph[j][1] = pack2(s[2*j][2], s[2*j][3]);
            ph[j][2] = pack2(s[2*j+1][0], s[2*j+1][1]);
            ph[j][3] = pack2(s[2*j+1][2], s[2*j+1][3]);
        }

        rs0 += __shfl_xor_sync(0xffffffffu, rs0, 1);
        rs0 += __shfl_xor_sync(0xffffffffu, rs0, 2);
        rs1 += __shfl_xor_sync(0xffffffffu, rs1, 1);
        rs1 += __shfl_xor_sync(0xffffffffu, rs1, 2);
        l0_ = l0_ * corr0 + rs0;
        l1_ = l1_ * corr1 + rs1;

        #pragma unroll
        for (int dt = 0; dt < 8; dt++) {
            o[dt][0] *= corr0; o[dt][1] *= corr0;
            o[dt][2] *= corr1; o[dt][3] *= corr1;
        }

        // ---- O += P . V ----
        #pragma unroll
        for (int j = 0; j < 4; j++) {
            uint32_t vb[4][4];
            #pragma unroll
            for (int dq = 0; dq < 4; dq++)
                ldsm4t(vb[dq], sV + (j * 16 + arow) * AP + (dq * 16 + akoff) * 2);
            #pragma unroll
            for (int dt = 0; dt < 8; dt++)
                mma16816(o[dt], ph[j], &vb[dt >> 1][(dt & 1) << 1]);
        }
        __syncthreads();
    }

    // ---- epilogue: normalize, store y (fp16) ----
    const float inv0 = 1.f / l0_, inv1 = 1.f / l1_;
    const int gr = b * SEQ + q0 + wid * 16 + (lane >> 2);
    const int col = h * HEADDIM + ((lane & 3) << 1);
    #pragma unroll
    for (int dt = 0; dt < 8; dt++) {
        *(uint32_t*)(y + (size_t)gr * HID + col + dt * 8) =
            pack2(o[dt][0] * inv0, o[dt][1] * inv0);
        *(uint32_t*)(y + (size_t)(gr + 8) * HID + col + dt * 8) =
            pack2(o[dt][2] * inv1, o[dt][3] * inv1);
    }
}

// ================= fused prep: act converts + 3 coalesced weight transposes ====
#define ACT_BLKS (MROWS * HID / 4 / 256)     // 4096
#define WQ_TILES ((HID / 64) * (HID / 64))       // 256
#define WKV_TILES ((2 * HID / 64) * (HID / 64))  // 512
#define WC_TILES WQ_TILES                        // 256

__device__ __forceinline__ void act_conv_blk(const float* __restrict__ in,
                                             fp16* __restrict__ h, int blk, int tid) {
    int i = ((blk * 256 + tid) << 2);
    float4 v = *(const float4*)(in + i);
    *(uint32_t*)(h + i)     = pack2(v.x, v.y);
    *(uint32_t*)(h + i + 2) = pack2(v.z, v.w);
}

// 64x64 transpose tile: W[K,Nstride] fp32 (pre-offset) -> T[N,K] fp16.
__device__ __forceinline__ void trconv64(const float* __restrict__ W, fp16* __restrict__ T,
                                         int Nstride, int n0, int k0, int tid,
                                         float* s /* [64*65] */) {
    #pragma unroll
    for (int i = 0; i < 4; i++) {
        int idx = tid + (i << 8);
        int r = idx >> 4, c4 = (idx & 15) << 2;
        float4 v = *(const float4*)(W + (size_t)(k0 + r) * Nstride + n0 + c4);
        s[r * 65 + c4 + 0] = v.x;
        s[r * 65 + c4 + 1] = v.y;
        s[r * 65 + c4 + 2] = v.z;
        s[r * 65 + c4 + 3] = v.w;
    }
    __syncthreads();
    const int n = tid >> 2, kk = (tid & 3) << 4;
    uint32_t o[8];
    #pragma unroll
    for (int i = 0; i < 8; i++)
        o[i] = pack2(s[(kk + 2 * i) * 65 + n], s[(kk + 2 * i + 1) * 65 + n]);
    fp16* dst = T + (size_t)(n0 + n) * HID + k0 + kk;
    *(uint4*)dst       = make_uint4(o[0], o[1], o[2], o[3]);
    *(uint4*)(dst + 8) = make_uint4(o[4], o[5], o[6], o[7]);
    __syncthreads();
}

__global__ void prep(const float* __restrict__ query, const float* __restrict__ key_value,
                     const float* __restrict__ Wq, const float* __restrict__ Wkv,
                     const float* __restrict__ Wc,
                     fp16* __restrict__ qin, fp16* __restrict__ kvin,
                     fp16* __restrict__ wqT, fp16* __restrict__ wkvT,
                     fp16* __restrict__ wcT) {
    __shared__ float s[64 * 65];
    const int tid = threadIdx.x;
    int b = blockIdx.x;
    if (b < ACT_BLKS) { act_conv_blk(query, qin, b, tid); return; }
    b -= ACT_BLKS;
    if (b < ACT_BLKS) { act_conv_blk(key_value, kvin, b, tid); return; }
    b -= ACT_BLKS;
    if (b < WQ_TILES) {
        int nt = b & 15, kt = b >> 4;
        trconv64(Wq, wqT, HID, nt << 6, kt << 6, tid, s);
        return;
    }
    b -= WQ_TILES;
    if (b < WKV_TILES) {
        int nt = b & 31, kt = b >> 5;
        trconv64(Wkv, wkvT, 2 * HID, nt << 6, kt << 6, tid, s);
        return;
    }
    b -= WKV_TILES;
    {
        int nt = b & 15, kt = b >> 4;
        trconv64(Wc, wcT, HID, nt << 6, kt << 6, tid, s);
    }
}

// ---------------- launch ----------------
extern "C" void kernel_launch(void* const* d_in, const int* in_sizes, int n_in,
                              void* d_out, int out_size) {
    const float* query     = (const float*)d_in[0];
    const float* key_value = (const float*)d_in[1];
    const float* Wq        = (const float*)d_in[2];
    const float* Wkv       = (const float*)d_in[3];
    const float* Wc        = (const float*)d_in[4];
    float* out = (float*)d_out;

    fp16 *qin, *kvin, *q, *kv, *y, *wqT, *wkvT, *wcT;
    cudaGetSymbolAddress((void**)&qin,  g_qin);
    cudaGetSymbolAddress((void**)&kvin, g_kvin);
    cudaGetSymbolAddress((void**)&q,    g_q);
    cudaGetSymbolAddress((void**)&kv,   g_kv);
    cudaGetSymbolAddress((void**)&y,    g_y);
    cudaGetSymbolAddress((void**)&wqT,  g_wqT);
    cudaGetSymbolAddress((void**)&wkvT, g_wkvT);
    cudaGetSymbolAddress((void**)&wcT,  g_wcT);

    cudaFuncSetAttribute(proj_gemm, cudaFuncAttributeMaxDynamicSharedMemorySize, GSMEM);
    cudaFuncSetAttribute(out_gemm,  cudaFuncAttributeMaxDynamicSharedMemorySize, GSMEM);
    cudaFuncSetAttribute(attn_mma,  cudaFuncAttributeMaxDynamicSharedMemorySize, ASMEM);

    // one fused prep launch: both act converts + all 3 weight transposes
    prep<<<2 * ACT_BLKS + WQ_TILES + WKV_TILES + WC_TILES, 256>>>(
        query, key_value, Wq, Wkv, Wc, qin, kvin, wqT, wkvT, wcT);

    // merged projections: bx<8 -> q-proj (QSCALE folded), else kv-proj
    proj_gemm<<<dim3(HID / 128 + 2 * HID / 128, MROWS / 128), 256, GSMEM>>>(
        qin, kvin, wqT, wkvT, q, kv);

    // attention: 64-query CTAs, 128 threads, 3 CTAs/SM
    attn_mma<<<dim3(SEQ / 64, BATCH * NHEADS), 128, ASMEM>>>(q, kv, y);

    out_gemm<<<dim3(HID / 128, MROWS / 128), 256, GSMEM>>>(y, wcT, out);
}